// round 5
// baseline (speedup 1.0000x reference)
#include <cuda_runtime.h>
#include <cuda_fp16.h>
#include <cstdint>
#include <math.h>

#define B_  16
#define L_  4096
#define D_  512
#define U_  450
#define UP_ 512
#define SCALE_ 0.04419417382415922f     // 1/sqrt(512)
typedef unsigned long long ull;

// ---------------- scratch -------------------------------------------------------
__device__ float g_q[(size_t)B_ * L_ * D_];
__device__ float g_k[(size_t)B_ * L_ * D_];
__device__ float g_v[(size_t)B_ * L_ * D_];
__device__ float g_qks [(size_t)B_ * L_ * UP_];
__device__ float g_attn[(size_t)B_ * UP_ * L_];
__device__ float g_ksamp[(size_t)B_ * UP_ * D_];  // rows >=450 stay zero
__device__ float g_qsel [(size_t)B_ * UP_ * D_];
__device__ float g_upd  [(size_t)B_ * UP_ * D_];
__device__ float g_M[B_ * L_];
__device__ int   g_top[B_ * U_];
__device__ float g_part[B_ * 8 * D_];

// ---------------- helpers -------------------------------------------------------
__device__ __forceinline__ void mma16816(float* c, const uint32_t* a, const uint32_t* b) {
    asm volatile(
        "mma.sync.aligned.m16n8k16.row.col.f32.f16.f16.f32 "
        "{%0,%1,%2,%3}, {%4,%5,%6,%7}, {%8,%9}, {%0,%1,%2,%3};"
        : "+f"(c[0]), "+f"(c[1]), "+f"(c[2]), "+f"(c[3])
        : "r"(a[0]), "r"(a[1]), "r"(a[2]), "r"(a[3]), "r"(b[0]), "r"(b[1]));
}
// fp16 smem XOR swizzle: rows of 16 uint32 (half2 words)
__device__ __forceinline__ int hwidx(int row, int w) {
    return (row << 4) | (w ^ ((row << 1) & 14));
}
__device__ __forceinline__ uint32_t packh2(float x, float y) {
    __half2 h = __floats2half2_rn(x, y);
    return *(uint32_t*)&h;
}
__device__ __forceinline__ float2 unpackh2f(uint32_t u) {
    __half2 h = *(__half2*)&u;
    return __half22float2(h);
}

// =================================================================================
// fp16 mma.sync GEMM, optional 2-way split (PASSES=3: hh+hl+lh ~ fp32 accuracy).
// C[m,n] = sum_k A[m,k]*B(n,k).  A pre-scaled by ascale (epilogue * 1/ascale).
//   TRANSB=false : B source is (N x K) row-major
//   TRANSB=true  : B source is (K x N) row-major, rows split at splitK (B1/B2)
// 256 thr, 8 warps (2Mx4N), block 128x128, K-tile 32, DOUBLE-BUFFERED smem
// (one __syncthreads per K-tile; next-tile gmem loads overlap compute).
// =================================================================================
template <bool TRANSB, int PASSES>
__global__ void __launch_bounds__(256, 1) gemm_h(
    const float* __restrict__ A, ull sA, int lda,
    const float* __restrict__ B1, const float* __restrict__ B2,
    ull sB, int ldb, int splitK,
    float* __restrict__ C, ull sC, int ldc,
    const float* __restrict__ bias, int K, float ascale, float inv_ascale)
{
    extern __shared__ __align__(16) uint32_t smh[];
    const int BW = (PASSES == 3 ? 4 : 2) * 2048;   // words per stage
    uint32_t* bufs[2] = { smh, smh + BW };

    const int tid = threadIdx.x;
    const int lane = tid & 31, wid = tid >> 5;
    const int g = lane >> 2, tig = lane & 3;
    const int wm = wid & 1, wn = wid >> 1;
    const int z = blockIdx.z;
    A  += (size_t)z * sA;
    B1 += (size_t)z * sB;
    B2 += (size_t)z * sB;
    C  += (size_t)z * sC;
    const int m0 = blockIdx.y * 128, n0 = blockIdx.x * 128;

    float acc[16][4];
#pragma unroll
    for (int i = 0; i < 16; i++)
#pragma unroll
        for (int j = 0; j < 4; j++) acc[i][j] = 0.f;

    float4 pA[4], pB[4];
    const int NT = K / 32;

    auto loadA = [&](int kt) {
        const float* Ab = A + (size_t)m0 * lda + kt * 32;
#pragma unroll
        for (int it = 0; it < 4; it++) {
            int task = tid + it * 256;
            int r = task >> 3, cq = task & 7;
            pA[it] = *(const float4*)(Ab + (size_t)r * lda + cq * 4);
        }
    };
    auto loadB = [&](int kt) {
        if (!TRANSB) {
            const float* Bb = B1 + (size_t)n0 * ldb + kt * 32;
#pragma unroll
            for (int it = 0; it < 4; it++) {
                int task = tid + it * 256;
                int r = task >> 3, cq = task & 7;
                pB[it] = *(const float4*)(Bb + (size_t)r * ldb + cq * 4);
            }
        } else {
#pragma unroll
            for (int it = 0; it < 4; it++) {
                int task = tid + it * 256;
                int n = task & 127, q = task >> 7;
                int kb = kt * 32 + q * 4;
                float vv[4];
#pragma unroll
                for (int i = 0; i < 4; i++) {
                    int kk = kb + i;
                    const float* row = (kk < splitK)
                        ? (B1 + (size_t)kk * ldb)
                        : (B2 + (size_t)(kk - splitK) * ldb);
                    vv[i] = row[n0 + n];
                }
                pB[it] = make_float4(vv[0], vv[1], vv[2], vv[3]);
            }
        }
    };
    auto stsAll = [&](uint32_t* base) {
        uint32_t* Ah = base;
        uint32_t* Bh = base + 2048;
        uint32_t* Al = base + 4096;   // only touched when PASSES==3
        uint32_t* Bl = base + 6144;
#pragma unroll
        for (int it = 0; it < 4; it++) {
            int task = tid + it * 256;
            {   // A (scaled)
                int r = task >> 3, cq = task & 7;
                float4 v = pA[it];
                v.x *= ascale; v.y *= ascale; v.z *= ascale; v.w *= ascale;
                uint32_t h0 = packh2(v.x, v.y), h1 = packh2(v.z, v.w);
                int w = (2 * cq) ^ ((r << 1) & 14);
                *(uint2*)&Ah[r * 16 + w] = make_uint2(h0, h1);
                if (PASSES == 3) {
                    float2 f0 = unpackh2f(h0), f1 = unpackh2f(h1);
                    *(uint2*)&Al[r * 16 + w] = make_uint2(
                        packh2(v.x - f0.x, v.y - f0.y),
                        packh2(v.z - f1.x, v.w - f1.y));
                }
            }
            {   // B
                int r, cq;
                if (!TRANSB) { r = task >> 3; cq = task & 7; }
                else         { r = task & 127; cq = task >> 7; }
                float4 v = pB[it];
                uint32_t h0 = packh2(v.x, v.y), h1 = packh2(v.z, v.w);
                int w = (2 * cq) ^ ((r << 1) & 14);
                *(uint2*)&Bh[r * 16 + w] = make_uint2(h0, h1);
                if (PASSES == 3) {
                    float2 f0 = unpackh2f(h0), f1 = unpackh2f(h1);
                    *(uint2*)&Bl[r * 16 + w] = make_uint2(
                        packh2(v.x - f0.x, v.y - f0.y),
                        packh2(v.z - f1.x, v.w - f1.y));
                }
            }
        }
    };
    auto compute = [&](uint32_t* base) {
        uint32_t* Ah = base;
        uint32_t* Bh = base + 2048;
        uint32_t* Al = base + 4096;
        uint32_t* Bl = base + 6144;
#pragma unroll
        for (int ks = 0; ks < 2; ks++) {           // two k=16 steps per K-tile 32
            const int wb = ks * 8;
            uint32_t ah[4][4], bh[4][2], al[4][4], bl[4][2];
#pragma unroll
            for (int mt = 0; mt < 4; mt++) {
                int r0 = wm * 64 + mt * 16 + g, r1 = r0 + 8;
                ah[mt][0] = Ah[hwidx(r0, wb + tig)];
                ah[mt][1] = Ah[hwidx(r1, wb + tig)];
                ah[mt][2] = Ah[hwidx(r0, wb + tig + 4)];
                ah[mt][3] = Ah[hwidx(r1, wb + tig + 4)];
                if (PASSES == 3) {
                    al[mt][0] = Al[hwidx(r0, wb + tig)];
                    al[mt][1] = Al[hwidx(r1, wb + tig)];
                    al[mt][2] = Al[hwidx(r0, wb + tig + 4)];
                    al[mt][3] = Al[hwidx(r1, wb + tig + 4)];
                }
            }
#pragma unroll
            for (int nt = 0; nt < 4; nt++) {
                int rn = wn * 32 + nt * 8 + g;
                bh[nt][0] = Bh[hwidx(rn, wb + tig)];
                bh[nt][1] = Bh[hwidx(rn, wb + tig + 4)];
                if (PASSES == 3) {
                    bl[nt][0] = Bl[hwidx(rn, wb + tig)];
                    bl[nt][1] = Bl[hwidx(rn, wb + tig + 4)];
                }
            }
#pragma unroll
            for (int mt = 0; mt < 4; mt++)
#pragma unroll
                for (int nt = 0; nt < 4; nt++) {
                    mma16816(acc[mt * 4 + nt], ah[mt], bh[nt]);
                    if (PASSES == 3) {
                        mma16816(acc[mt * 4 + nt], ah[mt], bl[nt]);
                        mma16816(acc[mt * 4 + nt], al[mt], bh[nt]);
                    }
                }
        }
    };

    // ---- pipelined mainloop: one __syncthreads per K-tile ----
    loadA(0); loadB(0);
    stsAll(bufs[0]);
    __syncthreads();
    for (int kt = 0; kt < NT; kt++) {
        if (kt + 1 < NT) { loadA(kt + 1); loadB(kt + 1); }
        compute(bufs[kt & 1]);
        if (kt + 1 < NT) {
            stsAll(bufs[(kt + 1) & 1]);
            __syncthreads();
        }
    }

#pragma unroll
    for (int mt = 0; mt < 4; mt++) {
        int r0 = m0 + wm * 64 + mt * 16 + g;
        float b0 = bias ? bias[r0] : 0.f;
        float b1 = bias ? bias[r0 + 8] : 0.f;
#pragma unroll
        for (int nt = 0; nt < 4; nt++) {
            int cc = n0 + wn * 32 + nt * 8 + 2 * tig;
            float* c = acc[mt * 4 + nt];
            *(float2*)(C + (size_t)r0 * ldc + cc) =
                make_float2(c[0] * inv_ascale + b0, c[1] * inv_ascale + b0);
            *(float2*)(C + (size_t)(r0 + 8) * ldc + cc) =
                make_float2(c[2] * inv_ascale + b1, c[3] * inv_ascale + b1);
        }
    }
}

// ---------------- small kernels --------------------------------------------------
__global__ void gather_ksamp(const int* __restrict__ idx)
{
    int b = blockIdx.y, u = blockIdx.x;
    int r = idx[u];
    const float4* s = (const float4*)(g_k + ((size_t)b * L_ + r) * D_);
    float4*       d = (float4*)(g_ksamp + ((size_t)b * UP_ + u) * D_);
    d[threadIdx.x] = s[threadIdx.x];
}

__global__ void mreduce_kernel()
{
    int b = blockIdx.y;
    int l = blockIdx.x * 8 + (threadIdx.x >> 5);
    int lane = threadIdx.x & 31;
    const float* row = g_qks + ((size_t)b * L_ + l) * UP_;
    float mx = -3.0e38f, sm = 0.f;
    for (int s = lane; s < U_; s += 32) { float v = row[s]; mx = fmaxf(mx, v); sm += v; }
#pragma unroll
    for (int o = 16; o; o >>= 1) {
        mx = fmaxf(mx, __shfl_xor_sync(0xffffffffu, mx, o));
        sm += __shfl_xor_sync(0xffffffffu, sm, o);
    }
    if (!lane) g_M[b * L_ + l] = mx - sm * (1.0f / 4096.0f);
}

__global__ void topk_kernel()
{
    __shared__ unsigned long long key[4096];
    int b = blockIdx.x;
    const float* m = g_M + b * L_;
    for (int i = threadIdx.x; i < 4096; i += 1024) {
        unsigned u = __float_as_uint(m[i]);
        u = (u & 0x80000000u) ? ~u : (u | 0x80000000u);
        key[i] = ((unsigned long long)u << 32) | (unsigned)(4095 - i);
    }
    __syncthreads();
    for (int k = 2; k <= 4096; k <<= 1) {
        for (int j = k >> 1; j > 0; j >>= 1) {
            for (int i = threadIdx.x; i < 4096; i += 1024) {
                int ixj = i ^ j;
                if (ixj > i) {
                    bool up = ((i & k) == 0);
                    unsigned long long a = key[i], c = key[ixj];
                    if ((a > c) == up) { key[i] = c; key[ixj] = a; }
                }
            }
            __syncthreads();
        }
    }
    for (int t = threadIdx.x; t < U_; t += 1024) {
        unsigned long long kk = key[4095 - t];
        g_top[b * U_ + t] = 4095 - (int)(unsigned)(kk & 0xFFFFFFFFu);
    }
}

__global__ void gather_qsel()
{
    int b = blockIdx.y, u = blockIdx.x;
    int r = g_top[b * U_ + u];
    const float4* s = (const float4*)(g_q + ((size_t)b * L_ + r) * D_);
    float4*       d = (float4*)(g_qsel + ((size_t)b * UP_ + u) * D_);
    d[threadIdx.x] = s[threadIdx.x];
}

__global__ void softmax_kernel()
{
    int b = blockIdx.y, u = blockIdx.x;
    float* row = g_attn + ((size_t)b * UP_ + (size_t)u) * L_;
    int tid = threadIdx.x;
    int lane = tid & 31, wid = tid >> 5;

    float v[16]; float mx = -3.0e38f;
#pragma unroll
    for (int i = 0; i < 16; i++) {
        float t = row[tid + i * 256] * SCALE_;
        v[i] = t; mx = fmaxf(mx, t);
    }
    __shared__ float red[8];
    __shared__ float bcast;
#pragma unroll
    for (int o = 16; o; o >>= 1) mx = fmaxf(mx, __shfl_xor_sync(0xffffffffu, mx, o));
    if (!lane) red[wid] = mx;
    __syncthreads();
    if (!tid) { float m2 = red[0]; for (int w = 1; w < 8; w++) m2 = fmaxf(m2, red[w]); bcast = m2; }
    __syncthreads();
    mx = bcast;

    float sm = 0.f;
#pragma unroll
    for (int i = 0; i < 16; i++) { v[i] = expf(v[i] - mx); sm += v[i]; }
#pragma unroll
    for (int o = 16; o; o >>= 1) sm += __shfl_xor_sync(0xffffffffu, sm, o);
    __syncthreads();
    if (!lane) red[wid] = sm;
    __syncthreads();
    if (!tid) { float s = red[0]; for (int w = 1; w < 8; w++) s += red[w]; bcast = 1.0f / s; }
    __syncthreads();
    float inv = bcast;
#pragma unroll
    for (int i = 0; i < 16; i++) row[tid + i * 256] = v[i] * inv;
}

__global__ void vmean_part()
{
    int b = blockIdx.y, ch = blockIdx.x;
    int d = threadIdx.x;
    const float* base = g_v + (size_t)b * L_ * D_ + (size_t)ch * 512 * D_ + d;
    float s = 0.f;
    for (int l = 0; l < 512; l++) s += base[(size_t)l * D_];
    g_part[(b * 8 + ch) * D_ + d] = s;
}

__global__ void fill_kernel(float* __restrict__ out)
{
    int b = blockIdx.y;
    int l0 = blockIdx.x * 8;
    int d = threadIdx.x;
    float s = 0.f;
#pragma unroll
    for (int c = 0; c < 8; c++) s += g_part[(b * 8 + c) * D_ + d];
    s *= (1.0f / 4096.0f);
    float* o = out + (size_t)b * L_ * D_ + (size_t)l0 * D_ + d;
#pragma unroll
    for (int r = 0; r < 8; r++) o[(size_t)r * D_] = s;
}

__global__ void scatter_kernel(float* __restrict__ out)
{
    int b = blockIdx.y, u = blockIdx.x;
    int r = g_top[b * U_ + u];
    const float4* s = (const float4*)(g_upd + ((size_t)b * UP_ + u) * D_);
    float4*       d = (float4*)(out + ((size_t)b * L_ + r) * D_);
    d[threadIdx.x] = s[threadIdx.x];
}

// =================================================================================
#define SMEM3 (2 * 4 * 2048 * 4)   // 64 KB (PASSES=3, double-buffered)
#define SMEM1 (2 * 2 * 2048 * 4)   // 32 KB (PASSES=1, double-buffered)

extern "C" void kernel_launch(void* const* d_in, const int* in_sizes, int n_in,
                              void* d_out, int out_size)
{
    const float* in1 = (const float*)d_in[0];
    const float* in2 = (const float*)d_in[1];
    const float* Wq  = (const float*)d_in[2];
    const float* bq  = (const float*)d_in[3];
    const float* Wk  = (const float*)d_in[4];
    const float* bk  = (const float*)d_in[5];
    const float* Wv  = (const float*)d_in[6];
    const float* bv  = (const float*)d_in[7];
    const int*   idx = (const int*)d_in[8];
    float* out = (float*)d_out;

    float *qp, *kp, *vp, *qksp, *attnp, *ksp, *qsp, *upp;
    cudaGetSymbolAddress((void**)&qp,   g_q);
    cudaGetSymbolAddress((void**)&kp,   g_k);
    cudaGetSymbolAddress((void**)&vp,   g_v);
    cudaGetSymbolAddress((void**)&qksp, g_qks);
    cudaGetSymbolAddress((void**)&attnp,g_attn);
    cudaGetSymbolAddress((void**)&ksp,  g_ksamp);
    cudaGetSymbolAddress((void**)&qsp,  g_qsel);
    cudaGetSymbolAddress((void**)&upp,  g_upd);

    cudaFuncSetAttribute(gemm_h<true, 3>,  cudaFuncAttributeMaxDynamicSharedMemorySize, SMEM3);
    cudaFuncSetAttribute(gemm_h<false, 3>, cudaFuncAttributeMaxDynamicSharedMemorySize, SMEM3);
    cudaFuncSetAttribute(gemm_h<true, 1>,  cudaFuncAttributeMaxDynamicSharedMemorySize, SMEM1);
    cudaFuncSetAttribute(gemm_h<false, 1>, cudaFuncAttributeMaxDynamicSharedMemorySize, SMEM1);

    const ull sX   = (ull)256 * 4096;
    const ull sQKV = (ull)L_ * D_;
    const float AS = 1024.f, IAS = 1.f / 1024.f;

    // 1. projections: q,k 3-product fp16 split (fp32-class), v 1 pass
    gemm_h<true, 3><<<dim3(32, 4, B_), 256, SMEM3>>>(
        Wq, 0ull, 512, in1, in2, sX, 4096, 256, qp, sQKV, 4096, bq, 512, AS, IAS);
    gemm_h<true, 3><<<dim3(32, 4, B_), 256, SMEM3>>>(
        Wk, 0ull, 512, in1, in2, sX, 4096, 256, kp, sQKV, 4096, bk, 512, AS, IAS);
    gemm_h<true, 1><<<dim3(32, 4, B_), 256, SMEM1>>>(
        Wv, 0ull, 512, in1, in2, sX, 4096, 256, vp, sQKV, 4096, bv, 512, AS, IAS);

    // 2. K_sample gather
    gather_ksamp<<<dim3(U_, B_), 128>>>(idx);

    // 3. QKs = q @ ksamp^T : fp16 3-product split (selection-critical, q scaled)
    gemm_h<false, 3><<<dim3(4, 32, B_), 256, SMEM3>>>(
        qp, sQKV, 512, ksp, ksp, (ull)UP_ * D_, 512, 512,
        qksp, (ull)L_ * UP_, UP_, nullptr, 512, AS, IAS);

    // 4-6. M reduce, top-450, Q_sel gather
    mreduce_kernel<<<dim3(512, B_), 256>>>();
    topk_kernel<<<B_, 1024>>>();
    gather_qsel<<<dim3(U_, B_), 128>>>();

    // 7. scores = Q_sel @ K^T : fp16 1-pass
    gemm_h<false, 1><<<dim3(32, 4, B_), 256, SMEM1>>>(
        qsp, (ull)UP_ * D_, 512, kp, kp, sQKV, 512, 512,
        attnp, (ull)UP_ * L_, 4096, nullptr, 512, 1.f, 1.f);

    // 8. softmax
    softmax_kernel<<<dim3(U_, B_), 256>>>();

    // 9. upd = attn @ V : fp16 1-pass, V is (K x N) -> TRANSB
    gemm_h<true, 1><<<dim3(4, 4, B_), 256, SMEM1>>>(
        attnp, (ull)UP_ * L_, 4096, vp, vp, sQKV, 512, 4096,
        upp, (ull)UP_ * D_, 512, nullptr, 4096, 1.f, 1.f);

    // 10. mean fill + scatter
    vmean_part<<<dim3(8, B_), 512>>>();
    fill_kernel<<<dim3(512, B_), 512>>>(out);
    scatter_kernel<<<dim3(U_, B_), 128>>>(out);
}

// round 6
// speedup vs baseline: 1.2881x; 1.2881x over previous
#include <cuda_runtime.h>
#include <cuda_fp16.h>
#include <cstdint>
#include <math.h>

#define B_  16
#define L_  4096
#define D_  512
#define U_  450
#define UP_ 512
#define SCALE_ 0.04419417382415922f     // 1/sqrt(512)
typedef unsigned long long ull;

// ---------------- scratch -------------------------------------------------------
__device__ float g_q[(size_t)B_ * L_ * D_];
__device__ float g_k[(size_t)B_ * L_ * D_];
__device__ float g_v[(size_t)B_ * L_ * D_];
__device__ float g_qks [(size_t)B_ * L_ * UP_];
__device__ float g_attn[(size_t)B_ * UP_ * L_];
__device__ float g_ksamp[(size_t)B_ * UP_ * D_];  // rows >=450 stay zero
__device__ float g_qsel [(size_t)B_ * UP_ * D_];
__device__ float g_upd  [(size_t)B_ * UP_ * D_];
__device__ float g_M[B_ * L_];
__device__ int   g_top[B_ * U_];
__device__ float g_part[B_ * 8 * D_];

// ---------------- helpers -------------------------------------------------------
__device__ __forceinline__ void mma16816(float* c, const uint32_t* a, const uint32_t* b) {
    asm volatile(
        "mma.sync.aligned.m16n8k16.row.col.f32.f16.f16.f32 "
        "{%0,%1,%2,%3}, {%4,%5,%6,%7}, {%8,%9}, {%0,%1,%2,%3};"
        : "+f"(c[0]), "+f"(c[1]), "+f"(c[2]), "+f"(c[3])
        : "r"(a[0]), "r"(a[1]), "r"(a[2]), "r"(a[3]), "r"(b[0]), "r"(b[1]));
}
// fp16 smem XOR swizzle: rows of 16 uint32 (half2 words)
__device__ __forceinline__ int hwidx(int row, int w) {
    return (row << 4) | (w ^ ((row << 1) & 14));
}
__device__ __forceinline__ uint32_t packh2(float x, float y) {
    __half2 h = __floats2half2_rn(x, y);
    return *(uint32_t*)&h;
}
__device__ __forceinline__ float2 unpackh2f(uint32_t u) {
    __half2 h = *(__half2*)&u;
    return __half22float2(h);
}

// =================================================================================
// fp16 mma.sync GEMM, optional 2-way split (PASSES=3: hh+hl+lh ~ fp32 accuracy).
// C[m,n] = sum_k A[m,k]*B(n,k).  A pre-scaled by ascale (epilogue * 1/ascale).
//   TRANSB=false : B source is (N x K) row-major
//   TRANSB=true  : B source is (K x N) row-major, rows split at splitK (B1/B2)
// 256 thr, 8 warps (2Mx4N), block 128x128, K-tile 32. Proven R4 loop structure:
// sts -> sync -> issue next-tile loads -> compute -> sync.
// =================================================================================
template <bool TRANSB, int PASSES>
__global__ void __launch_bounds__(256, 1) gemm_h(
    const float* __restrict__ A, ull sA, int lda,
    const float* __restrict__ B1, const float* __restrict__ B2,
    ull sB, int ldb, int splitK,
    float* __restrict__ C, ull sC, int ldc,
    const float* __restrict__ bias, int K, float ascale, float inv_ascale)
{
    __shared__ __align__(16) uint32_t smh[(PASSES == 3 ? 4 : 2) * 2048];
    uint32_t* Ah = smh;                      // 128 x 16 words
    uint32_t* Bh = smh + 2048;
    uint32_t* Al = (PASSES == 3) ? smh + 4096 : smh;
    uint32_t* Bl = (PASSES == 3) ? smh + 6144 : smh;

    const int tid = threadIdx.x;
    const int lane = tid & 31, wid = tid >> 5;
    const int g = lane >> 2, tig = lane & 3;
    const int wm = wid & 1, wn = wid >> 1;
    const int z = blockIdx.z;
    A  += (size_t)z * sA;
    B1 += (size_t)z * sB;
    B2 += (size_t)z * sB;
    C  += (size_t)z * sC;
    const int m0 = blockIdx.y * 128, n0 = blockIdx.x * 128;

    float acc[16][4];
#pragma unroll
    for (int i = 0; i < 16; i++)
#pragma unroll
        for (int j = 0; j < 4; j++) acc[i][j] = 0.f;

    float4 pA[4], pB[4];
    const int NT = K / 32;

    auto loadA = [&](int kt) {
        const float* Ab = A + (size_t)m0 * lda + kt * 32;
#pragma unroll
        for (int it = 0; it < 4; it++) {
            int task = tid + it * 256;
            int r = task >> 3, cq = task & 7;
            pA[it] = *(const float4*)(Ab + (size_t)r * lda + cq * 4);
        }
    };
    auto loadB = [&](int kt) {
        if (!TRANSB) {
            const float* Bb = B1 + (size_t)n0 * ldb + kt * 32;
#pragma unroll
            for (int it = 0; it < 4; it++) {
                int task = tid + it * 256;
                int r = task >> 3, cq = task & 7;
                pB[it] = *(const float4*)(Bb + (size_t)r * ldb + cq * 4);
            }
        } else {
#pragma unroll
            for (int it = 0; it < 4; it++) {
                int task = tid + it * 256;
                int n = task & 127, q = task >> 7;
                int kb = kt * 32 + q * 4;
                float vv[4];
#pragma unroll
                for (int i = 0; i < 4; i++) {
                    int kk = kb + i;
                    const float* row = (kk < splitK)
                        ? (B1 + (size_t)kk * ldb)
                        : (B2 + (size_t)(kk - splitK) * ldb);
                    vv[i] = row[n0 + n];
                }
                pB[it] = make_float4(vv[0], vv[1], vv[2], vv[3]);
            }
        }
    };
    auto stsAll = [&]() {
#pragma unroll
        for (int it = 0; it < 4; it++) {
            int task = tid + it * 256;
            {   // A (scaled)
                int r = task >> 3, cq = task & 7;
                float4 v = pA[it];
                v.x *= ascale; v.y *= ascale; v.z *= ascale; v.w *= ascale;
                uint32_t h0 = packh2(v.x, v.y), h1 = packh2(v.z, v.w);
                int w = (2 * cq) ^ ((r << 1) & 14);
                *(uint2*)&Ah[r * 16 + w] = make_uint2(h0, h1);
                if (PASSES == 3) {
                    float2 f0 = unpackh2f(h0), f1 = unpackh2f(h1);
                    *(uint2*)&Al[r * 16 + w] = make_uint2(
                        packh2(v.x - f0.x, v.y - f0.y),
                        packh2(v.z - f1.x, v.w - f1.y));
                }
            }
            {   // B
                int r, cq;
                if (!TRANSB) { r = task >> 3; cq = task & 7; }
                else         { r = task & 127; cq = task >> 7; }
                float4 v = pB[it];
                uint32_t h0 = packh2(v.x, v.y), h1 = packh2(v.z, v.w);
                int w = (2 * cq) ^ ((r << 1) & 14);
                *(uint2*)&Bh[r * 16 + w] = make_uint2(h0, h1);
                if (PASSES == 3) {
                    float2 f0 = unpackh2f(h0), f1 = unpackh2f(h1);
                    *(uint2*)&Bl[r * 16 + w] = make_uint2(
                        packh2(v.x - f0.x, v.y - f0.y),
                        packh2(v.z - f1.x, v.w - f1.y));
                }
            }
        }
    };

    loadA(0); loadB(0);
    for (int kt = 0; kt < NT; kt++) {
        stsAll();
        __syncthreads();
        if (kt + 1 < NT) { loadA(kt + 1); loadB(kt + 1); }
#pragma unroll
        for (int ks = 0; ks < 2; ks++) {           // two k=16 steps per K-tile 32
            const int wb = ks * 8;
            uint32_t ah[4][4], bh[4][2], al[4][4], bl[4][2];
#pragma unroll
            for (int mt = 0; mt < 4; mt++) {
                int r0 = wm * 64 + mt * 16 + g, r1 = r0 + 8;
                ah[mt][0] = Ah[hwidx(r0, wb + tig)];
                ah[mt][1] = Ah[hwidx(r1, wb + tig)];
                ah[mt][2] = Ah[hwidx(r0, wb + tig + 4)];
                ah[mt][3] = Ah[hwidx(r1, wb + tig + 4)];
                if (PASSES == 3) {
                    al[mt][0] = Al[hwidx(r0, wb + tig)];
                    al[mt][1] = Al[hwidx(r1, wb + tig)];
                    al[mt][2] = Al[hwidx(r0, wb + tig + 4)];
                    al[mt][3] = Al[hwidx(r1, wb + tig + 4)];
                }
            }
#pragma unroll
            for (int nt = 0; nt < 4; nt++) {
                int rn = wn * 32 + nt * 8 + g;
                bh[nt][0] = Bh[hwidx(rn, wb + tig)];
                bh[nt][1] = Bh[hwidx(rn, wb + tig + 4)];
                if (PASSES == 3) {
                    bl[nt][0] = Bl[hwidx(rn, wb + tig)];
                    bl[nt][1] = Bl[hwidx(rn, wb + tig + 4)];
                }
            }
#pragma unroll
            for (int mt = 0; mt < 4; mt++)
#pragma unroll
                for (int nt = 0; nt < 4; nt++) {
                    mma16816(acc[mt * 4 + nt], ah[mt], bh[nt]);
                    if (PASSES == 3) {
                        mma16816(acc[mt * 4 + nt], ah[mt], bl[nt]);
                        mma16816(acc[mt * 4 + nt], al[mt], bh[nt]);
                    }
                }
        }
        __syncthreads();
    }

#pragma unroll
    for (int mt = 0; mt < 4; mt++) {
        int r0 = m0 + wm * 64 + mt * 16 + g;
        float b0 = bias ? bias[r0] : 0.f;
        float b1 = bias ? bias[r0 + 8] : 0.f;
#pragma unroll
        for (int nt = 0; nt < 4; nt++) {
            int cc = n0 + wn * 32 + nt * 8 + 2 * tig;
            float* c = acc[mt * 4 + nt];
            *(float2*)(C + (size_t)r0 * ldc + cc) =
                make_float2(c[0] * inv_ascale + b0, c[1] * inv_ascale + b0);
            *(float2*)(C + (size_t)(r0 + 8) * ldc + cc) =
                make_float2(c[2] * inv_ascale + b1, c[3] * inv_ascale + b1);
        }
    }
}

// ---------------- small kernels --------------------------------------------------
__global__ void gather_ksamp(const int* __restrict__ idx)
{
    int b = blockIdx.y, u = blockIdx.x;
    int r = idx[u];
    const float4* s = (const float4*)(g_k + ((size_t)b * L_ + r) * D_);
    float4*       d = (float4*)(g_ksamp + ((size_t)b * UP_ + u) * D_);
    d[threadIdx.x] = s[threadIdx.x];
}

__global__ void mreduce_kernel()
{
    int b = blockIdx.y;
    int l = blockIdx.x * 8 + (threadIdx.x >> 5);
    int lane = threadIdx.x & 31;
    const float* row = g_qks + ((size_t)b * L_ + l) * UP_;
    float mx = -3.0e38f, sm = 0.f;
    for (int s = lane; s < U_; s += 32) { float v = row[s]; mx = fmaxf(mx, v); sm += v; }
#pragma unroll
    for (int o = 16; o; o >>= 1) {
        mx = fmaxf(mx, __shfl_xor_sync(0xffffffffu, mx, o));
        sm += __shfl_xor_sync(0xffffffffu, sm, o);
    }
    if (!lane) g_M[b * L_ + l] = mx - sm * (1.0f / 4096.0f);
}

__global__ void topk_kernel()
{
    __shared__ unsigned long long key[4096];
    int b = blockIdx.x;
    const float* m = g_M + b * L_;
    for (int i = threadIdx.x; i < 4096; i += 1024) {
        unsigned u = __float_as_uint(m[i]);
        u = (u & 0x80000000u) ? ~u : (u | 0x80000000u);
        key[i] = ((unsigned long long)u << 32) | (unsigned)(4095 - i);
    }
    __syncthreads();
    for (int k = 2; k <= 4096; k <<= 1) {
        for (int j = k >> 1; j > 0; j >>= 1) {
            for (int i = threadIdx.x; i < 4096; i += 1024) {
                int ixj = i ^ j;
                if (ixj > i) {
                    bool up = ((i & k) == 0);
                    unsigned long long a = key[i], c = key[ixj];
                    if ((a > c) == up) { key[i] = c; key[ixj] = a; }
                }
            }
            __syncthreads();
        }
    }
    for (int t = threadIdx.x; t < U_; t += 1024) {
        unsigned long long kk = key[4095 - t];
        g_top[b * U_ + t] = 4095 - (int)(unsigned)(kk & 0xFFFFFFFFu);
    }
}

__global__ void gather_qsel()
{
    int b = blockIdx.y, u = blockIdx.x;
    int r = g_top[b * U_ + u];
    const float4* s = (const float4*)(g_q + ((size_t)b * L_ + r) * D_);
    float4*       d = (float4*)(g_qsel + ((size_t)b * UP_ + u) * D_);
    d[threadIdx.x] = s[threadIdx.x];
}

__global__ void softmax_kernel()
{
    int b = blockIdx.y, u = blockIdx.x;
    float* row = g_attn + ((size_t)b * UP_ + (size_t)u) * L_;
    int tid = threadIdx.x;
    int lane = tid & 31, wid = tid >> 5;

    float v[16]; float mx = -3.0e38f;
#pragma unroll
    for (int i = 0; i < 16; i++) {
        float t = row[tid + i * 256] * SCALE_;
        v[i] = t; mx = fmaxf(mx, t);
    }
    __shared__ float red[8];
    __shared__ float bcast;
#pragma unroll
    for (int o = 16; o; o >>= 1) mx = fmaxf(mx, __shfl_xor_sync(0xffffffffu, mx, o));
    if (!lane) red[wid] = mx;
    __syncthreads();
    if (!tid) { float m2 = red[0]; for (int w = 1; w < 8; w++) m2 = fmaxf(m2, red[w]); bcast = m2; }
    __syncthreads();
    mx = bcast;

    float sm = 0.f;
#pragma unroll
    for (int i = 0; i < 16; i++) { v[i] = expf(v[i] - mx); sm += v[i]; }
#pragma unroll
    for (int o = 16; o; o >>= 1) sm += __shfl_xor_sync(0xffffffffu, sm, o);
    __syncthreads();
    if (!lane) red[wid] = sm;
    __syncthreads();
    if (!tid) { float s = red[0]; for (int w = 1; w < 8; w++) s += red[w]; bcast = 1.0f / s; }
    __syncthreads();
    float inv = bcast;
#pragma unroll
    for (int i = 0; i < 16; i++) row[tid + i * 256] = v[i] * inv;
}

__global__ void vmean_part()
{
    int b = blockIdx.y, ch = blockIdx.x;
    int d = threadIdx.x;
    const float* base = g_v + (size_t)b * L_ * D_ + (size_t)ch * 512 * D_ + d;
    float s = 0.f;
    for (int l = 0; l < 512; l++) s += base[(size_t)l * D_];
    g_part[(b * 8 + ch) * D_ + d] = s;
}

__global__ void fill_kernel(float* __restrict__ out)
{
    int b = blockIdx.y;
    int l0 = blockIdx.x * 8;
    int d = threadIdx.x;
    float s = 0.f;
#pragma unroll
    for (int c = 0; c < 8; c++) s += g_part[(b * 8 + c) * D_ + d];
    s *= (1.0f / 4096.0f);
    float* o = out + (size_t)b * L_ * D_ + (size_t)l0 * D_ + d;
#pragma unroll
    for (int r = 0; r < 8; r++) o[(size_t)r * D_] = s;
}

__global__ void scatter_kernel(float* __restrict__ out)
{
    int b = blockIdx.y, u = blockIdx.x;
    int r = g_top[b * U_ + u];
    const float4* s = (const float4*)(g_upd + ((size_t)b * UP_ + u) * D_);
    float4*       d = (float4*)(out + ((size_t)b * L_ + r) * D_);
    d[threadIdx.x] = s[threadIdx.x];
}

// =================================================================================
extern "C" void kernel_launch(void* const* d_in, const int* in_sizes, int n_in,
                              void* d_out, int out_size)
{
    const float* in1 = (const float*)d_in[0];
    const float* in2 = (const float*)d_in[1];
    const float* Wq  = (const float*)d_in[2];
    const float* bq  = (const float*)d_in[3];
    const float* Wk  = (const float*)d_in[4];
    const float* bk  = (const float*)d_in[5];
    const float* Wv  = (const float*)d_in[6];
    const float* bv  = (const float*)d_in[7];
    const int*   idx = (const int*)d_in[8];
    float* out = (float*)d_out;

    float *qp, *kp, *vp, *qksp, *attnp, *ksp, *qsp, *upp;
    cudaGetSymbolAddress((void**)&qp,   g_q);
    cudaGetSymbolAddress((void**)&kp,   g_k);
    cudaGetSymbolAddress((void**)&vp,   g_v);
    cudaGetSymbolAddress((void**)&qksp, g_qks);
    cudaGetSymbolAddress((void**)&attnp,g_attn);
    cudaGetSymbolAddress((void**)&ksp,  g_ksamp);
    cudaGetSymbolAddress((void**)&qsp,  g_qsel);
    cudaGetSymbolAddress((void**)&upp,  g_upd);

    const ull sX   = (ull)256 * 4096;
    const ull sQKV = (ull)L_ * D_;
    const float AS = 1024.f, IAS = 1.f / 1024.f;

    // 1. projections: q,k 3-product fp16 split (fp32-class), v 1 pass
    gemm_h<true, 3><<<dim3(32, 4, B_), 256>>>(
        Wq, 0ull, 512, in1, in2, sX, 4096, 256, qp, sQKV, 4096, bq, 512, AS, IAS);
    gemm_h<true, 3><<<dim3(32, 4, B_), 256>>>(
        Wk, 0ull, 512, in1, in2, sX, 4096, 256, kp, sQKV, 4096, bk, 512, AS, IAS);
    gemm_h<true, 1><<<dim3(32, 4, B_), 256>>>(
        Wv, 0ull, 512, in1, in2, sX, 4096, 256, vp, sQKV, 4096, bv, 512, AS, IAS);

    // 2. K_sample gather
    gather_ksamp<<<dim3(U_, B_), 128>>>(idx);

    // 3. QKs = q @ ksamp^T : fp16 3-product split (selection-critical, q scaled)
    gemm_h<false, 3><<<dim3(4, 32, B_), 256>>>(
        qp, sQKV, 512, ksp, ksp, (ull)UP_ * D_, 512, 512,
        qksp, (ull)L_ * UP_, UP_, nullptr, 512, AS, IAS);

    // 4-6. M reduce, top-450, Q_sel gather
    mreduce_kernel<<<dim3(512, B_), 256>>>();
    topk_kernel<<<B_, 1024>>>();
    gather_qsel<<<dim3(U_, B_), 128>>>();

    // 7. scores = Q_sel @ K^T : fp16 1-pass
    gemm_h<false, 1><<<dim3(32, 4, B_), 256>>>(
        qsp, (ull)UP_ * D_, 512, kp, kp, sQKV, 512, 512,
        attnp, (ull)UP_ * L_, 4096, nullptr, 512, 1.f, 1.f);

    // 8. softmax
    softmax_kernel<<<dim3(U_, B_), 256>>>();

    // 9. upd = attn @ V : fp16 1-pass, V is (K x N) -> TRANSB
    gemm_h<true, 1><<<dim3(4, 4, B_), 256>>>(
        attnp, (ull)UP_ * L_, 4096, vp, vp, sQKV, 512, 4096,
        upp, (ull)UP_ * D_, 512, nullptr, 4096, 1.f, 1.f);

    // 10. mean fill + scatter
    vmean_part<<<dim3(8, B_), 512>>>();
    fill_kernel<<<dim3(512, B_), 512>>>(out);
    scatter_kernel<<<dim3(U_, B_), 128>>>(out);
}

// round 7
// speedup vs baseline: 1.3374x; 1.0383x over previous
#include <cuda_runtime.h>
#include <cuda_fp16.h>
#include <cstdint>
#include <math.h>

#define B_  16
#define L_  4096
#define D_  512
#define U_  450
#define UP_ 512
#define SCALE_ 0.04419417382415922f     // 1/sqrt(512)
typedef unsigned long long ull;

// ---------------- scratch -------------------------------------------------------
__device__ float g_q[(size_t)B_ * L_ * D_];
__device__ float g_k[(size_t)B_ * L_ * D_];
__device__ float g_v[(size_t)B_ * L_ * D_];
__device__ float g_attn[(size_t)B_ * UP_ * L_];
__device__ float g_ksamp[(size_t)B_ * UP_ * D_];  // rows >=450 stay zero
__device__ float g_qsel [(size_t)B_ * UP_ * D_];
__device__ float g_upd  [(size_t)B_ * UP_ * D_];
__device__ float2 g_mpart[(size_t)B_ * L_ * 4];   // per-(l, n-tile) {max, sum}
__device__ float g_M[B_ * L_];
__device__ int   g_top[B_ * U_];
__device__ float g_part[B_ * 8 * D_];

// ---------------- helpers -------------------------------------------------------
__device__ __forceinline__ void mma16816(float* c, const uint32_t* a, const uint32_t* b) {
    asm volatile(
        "mma.sync.aligned.m16n8k16.row.col.f32.f16.f16.f32 "
        "{%0,%1,%2,%3}, {%4,%5,%6,%7}, {%8,%9}, {%0,%1,%2,%3};"
        : "+f"(c[0]), "+f"(c[1]), "+f"(c[2]), "+f"(c[3])
        : "r"(a[0]), "r"(a[1]), "r"(a[2]), "r"(a[3]), "r"(b[0]), "r"(b[1]));
}
// fp16 smem XOR swizzle: rows of 16 uint32 (half2 words)
__device__ __forceinline__ int hwidx(int row, int w) {
    return (row << 4) | (w ^ ((row << 1) & 14));
}
__device__ __forceinline__ uint32_t packh2(float x, float y) {
    __half2 h = __floats2half2_rn(x, y);
    return *(uint32_t*)&h;
}
__device__ __forceinline__ float2 unpackh2f(uint32_t u) {
    __half2 h = *(__half2*)&u;
    return __half22float2(h);
}

// =================================================================================
// fp16 mma.sync GEMM, optional 2-way split (PASSES=3: hh+hl+lh ~ fp32 accuracy).
// C[m,n] = sum_k A[m,k]*B(n,k).  A pre-scaled by ascale (epilogue * 1/ascale).
//   TRANSB=false : B source is (N x K) row-major
//   TRANSB=true  : B source is (K x N) row-major, rows split at splitK (B1/B2)
//   REDUCE=true  : do NOT write C; instead reduce per-row {max, sum} over this
//                  block's 128 columns (cols >= U_ masked out) into mpart
//                  [b, m, blockIdx.x] = {max, sum}.  (QKs -> M fusion.)
// 256 thr, 8 warps (2Mx4N), block 128x128, K-tile 32.
// Loop structure: sts -> sync -> issue next-tile loads -> compute -> sync.
// =================================================================================
template <bool TRANSB, int PASSES, bool REDUCE>
__global__ void __launch_bounds__(256, 1) gemm_h(
    const float* __restrict__ A, ull sA, int lda,
    const float* __restrict__ B1, const float* __restrict__ B2,
    ull sB, int ldb, int splitK,
    float* __restrict__ C, ull sC, int ldc,
    const float* __restrict__ bias, int K, float ascale, float inv_ascale,
    float2* __restrict__ mpart)
{
    __shared__ __align__(16) uint32_t smh[(PASSES == 3 ? 4 : 2) * 2048];
    uint32_t* Ah = smh;                      // 128 x 16 words
    uint32_t* Bh = smh + 2048;
    uint32_t* Al = (PASSES == 3) ? smh + 4096 : smh;
    uint32_t* Bl = (PASSES == 3) ? smh + 6144 : smh;

    const int tid = threadIdx.x;
    const int lane = tid & 31, wid = tid >> 5;
    const int g = lane >> 2, tig = lane & 3;
    const int wm = wid & 1, wn = wid >> 1;
    const int z = blockIdx.z;
    A  += (size_t)z * sA;
    B1 += (size_t)z * sB;
    B2 += (size_t)z * sB;
    C  += (size_t)z * sC;
    const int m0 = blockIdx.y * 128, n0 = blockIdx.x * 128;

    float acc[16][4];
#pragma unroll
    for (int i = 0; i < 16; i++)
#pragma unroll
        for (int j = 0; j < 4; j++) acc[i][j] = 0.f;

    float4 pA[4], pB[4];
    const int NT = K / 32;

    auto loadA = [&](int kt) {
        const float* Ab = A + (size_t)m0 * lda + kt * 32;
#pragma unroll
        for (int it = 0; it < 4; it++) {
            int task = tid + it * 256;
            int r = task >> 3, cq = task & 7;
            pA[it] = *(const float4*)(Ab + (size_t)r * lda + cq * 4);
        }
    };
    auto loadB = [&](int kt) {
        if (!TRANSB) {
            const float* Bb = B1 + (size_t)n0 * ldb + kt * 32;
#pragma unroll
            for (int it = 0; it < 4; it++) {
                int task = tid + it * 256;
                int r = task >> 3, cq = task & 7;
                pB[it] = *(const float4*)(Bb + (size_t)r * ldb + cq * 4);
            }
        } else {
#pragma unroll
            for (int it = 0; it < 4; it++) {
                int task = tid + it * 256;
                int n = task & 127, q = task >> 7;
                int kb = kt * 32 + q * 4;
                float vv[4];
#pragma unroll
                for (int i = 0; i < 4; i++) {
                    int kk = kb + i;
                    const float* row = (kk < splitK)
                        ? (B1 + (size_t)kk * ldb)
                        : (B2 + (size_t)(kk - splitK) * ldb);
                    vv[i] = row[n0 + n];
                }
                pB[it] = make_float4(vv[0], vv[1], vv[2], vv[3]);
            }
        }
    };
    auto stsAll = [&]() {
#pragma unroll
        for (int it = 0; it < 4; it++) {
            int task = tid + it * 256;
            {   // A (scaled)
                int r = task >> 3, cq = task & 7;
                float4 v = pA[it];
                v.x *= ascale; v.y *= ascale; v.z *= ascale; v.w *= ascale;
                uint32_t h0 = packh2(v.x, v.y), h1 = packh2(v.z, v.w);
                int w = (2 * cq) ^ ((r << 1) & 14);
                *(uint2*)&Ah[r * 16 + w] = make_uint2(h0, h1);
                if (PASSES == 3) {
                    float2 f0 = unpackh2f(h0), f1 = unpackh2f(h1);
                    *(uint2*)&Al[r * 16 + w] = make_uint2(
                        packh2(v.x - f0.x, v.y - f0.y),
                        packh2(v.z - f1.x, v.w - f1.y));
                }
            }
            {   // B
                int r, cq;
                if (!TRANSB) { r = task >> 3; cq = task & 7; }
                else         { r = task & 127; cq = task >> 7; }
                float4 v = pB[it];
                uint32_t h0 = packh2(v.x, v.y), h1 = packh2(v.z, v.w);
                int w = (2 * cq) ^ ((r << 1) & 14);
                *(uint2*)&Bh[r * 16 + w] = make_uint2(h0, h1);
                if (PASSES == 3) {
                    float2 f0 = unpackh2f(h0), f1 = unpackh2f(h1);
                    *(uint2*)&Bl[r * 16 + w] = make_uint2(
                        packh2(v.x - f0.x, v.y - f0.y),
                        packh2(v.z - f1.x, v.w - f1.y));
                }
            }
        }
    };

    loadA(0); loadB(0);
    for (int kt = 0; kt < NT; kt++) {
        stsAll();
        __syncthreads();
        if (kt + 1 < NT) { loadA(kt + 1); loadB(kt + 1); }
#pragma unroll
        for (int ks = 0; ks < 2; ks++) {           // two k=16 steps per K-tile 32
            const int wb = ks * 8;
            uint32_t ah[4][4], bh[4][2], al[4][4], bl[4][2];
#pragma unroll
            for (int mt = 0; mt < 4; mt++) {
                int r0 = wm * 64 + mt * 16 + g, r1 = r0 + 8;
                ah[mt][0] = Ah[hwidx(r0, wb + tig)];
                ah[mt][1] = Ah[hwidx(r1, wb + tig)];
                ah[mt][2] = Ah[hwidx(r0, wb + tig + 4)];
                ah[mt][3] = Ah[hwidx(r1, wb + tig + 4)];
                if (PASSES == 3) {
                    al[mt][0] = Al[hwidx(r0, wb + tig)];
                    al[mt][1] = Al[hwidx(r1, wb + tig)];
                    al[mt][2] = Al[hwidx(r0, wb + tig + 4)];
                    al[mt][3] = Al[hwidx(r1, wb + tig + 4)];
                }
            }
#pragma unroll
            for (int nt = 0; nt < 4; nt++) {
                int rn = wn * 32 + nt * 8 + g;
                bh[nt][0] = Bh[hwidx(rn, wb + tig)];
                bh[nt][1] = Bh[hwidx(rn, wb + tig + 4)];
                if (PASSES == 3) {
                    bl[nt][0] = Bl[hwidx(rn, wb + tig)];
                    bl[nt][1] = Bl[hwidx(rn, wb + tig + 4)];
                }
            }
#pragma unroll
            for (int mt = 0; mt < 4; mt++)
#pragma unroll
                for (int nt = 0; nt < 4; nt++) {
                    mma16816(acc[mt * 4 + nt], ah[mt], bh[nt]);
                    if (PASSES == 3) {
                        mma16816(acc[mt * 4 + nt], ah[mt], bl[nt]);
                        mma16816(acc[mt * 4 + nt], al[mt], bh[nt]);
                    }
                }
        }
        __syncthreads();
    }

    if (!REDUCE) {
#pragma unroll
        for (int mt = 0; mt < 4; mt++) {
            int r0 = m0 + wm * 64 + mt * 16 + g;
            float b0 = bias ? bias[r0] : 0.f;
            float b1 = bias ? bias[r0 + 8] : 0.f;
#pragma unroll
            for (int nt = 0; nt < 4; nt++) {
                int cc = n0 + wn * 32 + nt * 8 + 2 * tig;
                float* c = acc[mt * 4 + nt];
                *(float2*)(C + (size_t)r0 * ldc + cc) =
                    make_float2(c[0] * inv_ascale + b0, c[1] * inv_ascale + b0);
                *(float2*)(C + (size_t)(r0 + 8) * ldc + cc) =
                    make_float2(c[2] * inv_ascale + b1, c[3] * inv_ascale + b1);
            }
        }
    } else {
        // ---- fused per-row {max, sum} over this block's 128 columns ----
        float* smax = (float*)smh;            // [128 rows][4 wn]
        float* ssum = smax + 512;
#pragma unroll
        for (int mt = 0; mt < 4; mt++) {
            float m0v = -3.0e38f, s0v = 0.f;  // row r0
            float m1v = -3.0e38f, s1v = 0.f;  // row r1
#pragma unroll
            for (int nt = 0; nt < 4; nt++) {
                int cc = n0 + wn * 32 + nt * 8 + 2 * tig;
                float* c = acc[mt * 4 + nt];
#pragma unroll
                for (int e = 0; e < 2; e++) {
                    if (cc + e < U_) {
                        float v0 = c[0 + e] * inv_ascale;
                        float v1 = c[2 + e] * inv_ascale;
                        m0v = fmaxf(m0v, v0); s0v += v0;
                        m1v = fmaxf(m1v, v1); s1v += v1;
                    }
                }
            }
            // combine the 4 tig-lanes that share each row
#pragma unroll
            for (int off = 1; off <= 2; off <<= 1) {
                m0v = fmaxf(m0v, __shfl_xor_sync(0xffffffffu, m0v, off));
                s0v += __shfl_xor_sync(0xffffffffu, s0v, off);
                m1v = fmaxf(m1v, __shfl_xor_sync(0xffffffffu, m1v, off));
                s1v += __shfl_xor_sync(0xffffffffu, s1v, off);
            }
            if (tig == 0) {
                int r0 = wm * 64 + mt * 16 + g;
                smax[r0 * 4 + wn] = m0v;       ssum[r0 * 4 + wn] = s0v;
                smax[(r0 + 8) * 4 + wn] = m1v; ssum[(r0 + 8) * 4 + wn] = s1v;
            }
        }
        __syncthreads();
        if (tid < 128) {
            float mx = smax[tid * 4];
            float sm = ssum[tid * 4];
#pragma unroll
            for (int w = 1; w < 4; w++) {
                mx = fmaxf(mx, smax[tid * 4 + w]);
                sm += ssum[tid * 4 + w];
            }
            mpart[((size_t)z * L_ + m0 + tid) * 4 + blockIdx.x] = make_float2(mx, sm);
        }
    }
}

// ---------------- small kernels --------------------------------------------------
__global__ void gather_ksamp(const int* __restrict__ idx)
{
    int b = blockIdx.y, u = blockIdx.x;
    int r = idx[u];
    const float4* s = (const float4*)(g_k + ((size_t)b * L_ + r) * D_);
    float4*       d = (float4*)(g_ksamp + ((size_t)b * UP_ + u) * D_);
    d[threadIdx.x] = s[threadIdx.x];
}

// ---------------- M[l] = max over 4 partials - sum/4096 ------------------------
__global__ void mfinal_kernel()
{
    int i = blockIdx.x * 256 + threadIdx.x;           // i = b*L + l
    const float2* p = &g_mpart[(size_t)i * 4];
    float mx = p[0].x, sm = p[0].y;
#pragma unroll
    for (int w = 1; w < 4; w++) { mx = fmaxf(mx, p[w].x); sm += p[w].y; }
    g_M[i] = mx - sm * (1.0f / 4096.0f);
}

__global__ void topk_kernel()
{
    __shared__ unsigned long long key[4096];
    int b = blockIdx.x;
    const float* m = g_M + b * L_;
    for (int i = threadIdx.x; i < 4096; i += 1024) {
        unsigned u = __float_as_uint(m[i]);
        u = (u & 0x80000000u) ? ~u : (u | 0x80000000u);
        key[i] = ((unsigned long long)u << 32) | (unsigned)(4095 - i);
    }
    __syncthreads();
    for (int k = 2; k <= 4096; k <<= 1) {
        for (int j = k >> 1; j > 0; j >>= 1) {
            for (int i = threadIdx.x; i < 4096; i += 1024) {
                int ixj = i ^ j;
                if (ixj > i) {
                    bool up = ((i & k) == 0);
                    unsigned long long a = key[i], c = key[ixj];
                    if ((a > c) == up) { key[i] = c; key[ixj] = a; }
                }
            }
            __syncthreads();
        }
    }
    for (int t = threadIdx.x; t < U_; t += 1024) {
        unsigned long long kk = key[4095 - t];
        g_top[b * U_ + t] = 4095 - (int)(unsigned)(kk & 0xFFFFFFFFu);
    }
}

__global__ void gather_qsel()
{
    int b = blockIdx.y, u = blockIdx.x;
    int r = g_top[b * U_ + u];
    const float4* s = (const float4*)(g_q + ((size_t)b * L_ + r) * D_);
    float4*       d = (float4*)(g_qsel + ((size_t)b * UP_ + u) * D_);
    d[threadIdx.x] = s[threadIdx.x];
}

__global__ void softmax_kernel()
{
    int b = blockIdx.y, u = blockIdx.x;
    float* row = g_attn + ((size_t)b * UP_ + (size_t)u) * L_;
    int tid = threadIdx.x;
    int lane = tid & 31, wid = tid >> 5;

    float v[16]; float mx = -3.0e38f;
#pragma unroll
    for (int i = 0; i < 16; i++) {
        float t = row[tid + i * 256] * SCALE_;
        v[i] = t; mx = fmaxf(mx, t);
    }
    __shared__ float red[8];
    __shared__ float bcast;
#pragma unroll
    for (int o = 16; o; o >>= 1) mx = fmaxf(mx, __shfl_xor_sync(0xffffffffu, mx, o));
    if (!lane) red[wid] = mx;
    __syncthreads();
    if (!tid) { float m2 = red[0]; for (int w = 1; w < 8; w++) m2 = fmaxf(m2, red[w]); bcast = m2; }
    __syncthreads();
    mx = bcast;

    float sm = 0.f;
#pragma unroll
    for (int i = 0; i < 16; i++) { v[i] = expf(v[i] - mx); sm += v[i]; }
#pragma unroll
    for (int o = 16; o; o >>= 1) sm += __shfl_xor_sync(0xffffffffu, sm, o);
    __syncthreads();
    if (!lane) red[wid] = sm;
    __syncthreads();
    if (!tid) { float s = red[0]; for (int w = 1; w < 8; w++) s += red[w]; bcast = 1.0f / s; }
    __syncthreads();
    float inv = bcast;
#pragma unroll
    for (int i = 0; i < 16; i++) row[tid + i * 256] = v[i] * inv;
}

__global__ void vmean_part()
{
    int b = blockIdx.y, ch = blockIdx.x;
    int d = threadIdx.x;
    const float* base = g_v + (size_t)b * L_ * D_ + (size_t)ch * 512 * D_ + d;
    float s = 0.f;
    for (int l = 0; l < 512; l++) s += base[(size_t)l * D_];
    g_part[(b * 8 + ch) * D_ + d] = s;
}

__global__ void fill_kernel(float* __restrict__ out)
{
    int b = blockIdx.y;
    int l0 = blockIdx.x * 8;
    int d = threadIdx.x;
    float s = 0.f;
#pragma unroll
    for (int c = 0; c < 8; c++) s += g_part[(b * 8 + c) * D_ + d];
    s *= (1.0f / 4096.0f);
    float* o = out + (size_t)b * L_ * D_ + (size_t)l0 * D_ + d;
#pragma unroll
    for (int r = 0; r < 8; r++) o[(size_t)r * D_] = s;
}

__global__ void scatter_kernel(float* __restrict__ out)
{
    int b = blockIdx.y, u = blockIdx.x;
    int r = g_top[b * U_ + u];
    const float4* s = (const float4*)(g_upd + ((size_t)b * UP_ + u) * D_);
    float4*       d = (float4*)(out + ((size_t)b * L_ + r) * D_);
    d[threadIdx.x] = s[threadIdx.x];
}

// =================================================================================
extern "C" void kernel_launch(void* const* d_in, const int* in_sizes, int n_in,
                              void* d_out, int out_size)
{
    const float* in1 = (const float*)d_in[0];
    const float* in2 = (const float*)d_in[1];
    const float* Wq  = (const float*)d_in[2];
    const float* bq  = (const float*)d_in[3];
    const float* Wk  = (const float*)d_in[4];
    const float* bk  = (const float*)d_in[5];
    const float* Wv  = (const float*)d_in[6];
    const float* bv  = (const float*)d_in[7];
    const int*   idx = (const int*)d_in[8];
    float* out = (float*)d_out;

    float *qp, *kp, *vp, *attnp, *ksp, *qsp, *upp;
    float2* mpp;
    cudaGetSymbolAddress((void**)&qp,   g_q);
    cudaGetSymbolAddress((void**)&kp,   g_k);
    cudaGetSymbolAddress((void**)&vp,   g_v);
    cudaGetSymbolAddress((void**)&attnp,g_attn);
    cudaGetSymbolAddress((void**)&ksp,  g_ksamp);
    cudaGetSymbolAddress((void**)&qsp,  g_qsel);
    cudaGetSymbolAddress((void**)&upp,  g_upd);
    cudaGetSymbolAddress((void**)&mpp,  g_mpart);

    const ull sX   = (ull)256 * 4096;
    const ull sQKV = (ull)L_ * D_;
    const float AS = 1024.f, IAS = 1.f / 1024.f;

    // 1. projections: q,k 3-product fp16 split (fp32-class), v 1 pass
    gemm_h<true, 3, false><<<dim3(32, 4, B_), 256>>>(
        Wq, 0ull, 512, in1, in2, sX, 4096, 256, qp, sQKV, 4096, bq, 512, AS, IAS, nullptr);
    gemm_h<true, 3, false><<<dim3(32, 4, B_), 256>>>(
        Wk, 0ull, 512, in1, in2, sX, 4096, 256, kp, sQKV, 4096, bk, 512, AS, IAS, nullptr);
    gemm_h<true, 1, false><<<dim3(32, 4, B_), 256>>>(
        Wv, 0ull, 512, in1, in2, sX, 4096, 256, vp, sQKV, 4096, bv, 512, AS, IAS, nullptr);

    // 2. K_sample gather
    gather_ksamp<<<dim3(U_, B_), 128>>>(idx);

    // 3. QKs = q @ ksamp^T, fused with per-row {max,sum} reduction (no C write)
    gemm_h<false, 3, true><<<dim3(4, 32, B_), 256>>>(
        qp, sQKV, 512, ksp, ksp, (ull)UP_ * D_, 512, 512,
        nullptr, 0ull, 0, nullptr, 512, AS, IAS, mpp);

    // 4-6. M finalize, top-450, Q_sel gather
    mfinal_kernel<<<(B_ * L_) / 256, 256>>>();
    topk_kernel<<<B_, 1024>>>();
    gather_qsel<<<dim3(U_, B_), 128>>>();

    // 7. scores = Q_sel @ K^T : fp16 1-pass
    gemm_h<false, 1, false><<<dim3(32, 4, B_), 256>>>(
        qsp, (ull)UP_ * D_, 512, kp, kp, sQKV, 512, 512,
        attnp, (ull)UP_ * L_, 4096, nullptr, 512, 1.f, 1.f, nullptr);

    // 8. softmax
    softmax_kernel<<<dim3(U_, B_), 256>>>();

    // 9. upd = attn @ V : fp16 1-pass, V is (K x N) -> TRANSB
    gemm_h<true, 1, false><<<dim3(4, 4, B_), 256>>>(
        attnp, (ull)UP_ * L_, 4096, vp, vp, sQKV, 512, 4096,
        upp, (ull)UP_ * D_, 512, nullptr, 4096, 1.f, 1.f, nullptr);

    // 10. mean fill + scatter
    vmean_part<<<dim3(8, B_), 512>>>();
    fill_kernel<<<dim3(512, B_), 512>>>(out);
    scatter_kernel<<<dim3(U_, B_), 128>>>(out);
}